// round 1
// baseline (speedup 1.0000x reference)
#include <cuda_runtime.h>
#include <math.h>

#define B_ 2
#define N_ 2048
#define H_ 16
#define D_ 64
#define NCOLS 12          // log2(N)+1
#define SCALE 0.125f      // 1/sqrt(64)

// Parent-node scratch: nodes N_ .. 2N_-2 (N_-1 nodes per batch), layout [B, node, H, D]
__device__ float g_nodeK[B_ * (N_ - 1) * H_ * D_];
__device__ float g_nodeV[B_ * (N_ - 1) * H_ * D_];

__device__ __forceinline__ float warpReduceSum(float v) {
    v += __shfl_xor_sync(0xffffffffu, v, 16);
    v += __shfl_xor_sync(0xffffffffu, v, 8);
    v += __shfl_xor_sync(0xffffffffu, v, 4);
    v += __shfl_xor_sync(0xffffffffu, v, 2);
    v += __shfl_xor_sync(0xffffffffu, v, 1);
    return v;
}

// Build one tree level: each warp computes one parent node for one (b,h).
// Children come from leaves (K,V inputs) when childIsLeaf, else from scratch.
__global__ void build_level_kernel(const float* __restrict__ leafK,
                                   const float* __restrict__ leafV,
                                   int childIsLeaf,
                                   int childNN,      // node-dim extent of child buffer
                                   int childBase,    // local base of child level in its buffer
                                   int parentBase,   // local base of parent level in scratch
                                   int P)            // parents per (b,h)
{
    int warpGlobal = (int)((blockIdx.x * blockDim.x + threadIdx.x) >> 5);
    int lane = threadIdx.x & 31;
    int total = B_ * H_ * P;
    if (warpGlobal >= total) return;

    int h = warpGlobal % H_;
    int j = (warpGlobal / H_) % P;
    int b = warpGlobal / (H_ * P);

    const float* cK = childIsLeaf ? leafK : g_nodeK;
    const float* cV = childIsLeaf ? leafV : g_nodeV;

    int off0 = ((b * childNN + childBase + 2 * j) * H_ + h) * D_;
    int off1 = off0 + H_ * D_;

    float k0a = cK[off0 + lane], k0b = cK[off0 + lane + 32];
    float k1a = cK[off1 + lane], k1b = cK[off1 + lane + 32];
    float v0a = cV[off0 + lane], v0b = cV[off0 + lane + 32];
    float v1a = cV[off1 + lane], v1b = cV[off1 + lane + 32];

    float kpa = 0.5f * (k0a + k1a), kpb = 0.5f * (k0b + k1b);
    float vpa = 0.5f * (v0a + v1a), vpb = 0.5f * (v0b + v1b);

    float ss = warpReduceSum(kpa * kpa + kpb * kpb) * SCALE;
    float s0 = warpReduceSum(kpa * k0a + kpb * k0b) * SCALE;
    float s1 = warpReduceSum(kpa * k1a + kpb * k1b) * SCALE;

    float m = fmaxf(ss, fmaxf(s0, s1));
    float es = expf(ss - m), e0 = expf(s0 - m), e1 = expf(s1 - m);
    float inv = 1.0f / (es + e0 + e1 + 1e-9f);
    float ws = es * inv, w0 = e0 * inv, w1 = e1 * inv;

    int po = ((b * (N_ - 1) + parentBase + j) * H_ + h) * D_;
    g_nodeK[po + lane]      = ws * kpa + w0 * k0a + w1 * k1a;
    g_nodeK[po + lane + 32] = ws * kpb + w0 * k0b + w1 * k1b;
    g_nodeV[po + lane]      = ws * vpa + w0 * v0a + w1 * v1a;
    g_nodeV[po + lane + 32] = ws * vpb + w0 * v0b + w1 * v1b;
}

// Sparse attention: one warp per (b,n,h). 12 gathered nodes, softmax, weighted V sum.
__global__ void attn_kernel(const float* __restrict__ Q,
                            const float* __restrict__ K,
                            const float* __restrict__ V,
                            float* __restrict__ out)
{
    int warpGlobal = (int)((blockIdx.x * blockDim.x + threadIdx.x) >> 5);
    int lane = threadIdx.x & 31;
    if (warpGlobal >= B_ * N_ * H_) return;

    int h = warpGlobal % H_;
    int n = (warpGlobal / H_) % N_;
    int b = warpGlobal / (H_ * N_);

    // In-register hierarchical index table (faithful to _build_idx_table).
    int node[NCOLS];
    unsigned maskbits = 0u;
    node[0] = n;
    int ncur = n;
#pragma unroll
    for (int lvl = 1; lvl < NCOLS; lvl++) {
        int pair, nnext;
        if (lvl == 1) { nnext = ncur ^ 1; pair = ncur; }
        else          { pair = (ncur >> 1) + N_; nnext = pair ^ 1; }
        bool valid = (nnext <= 2 * N_ - 3);
        node[lvl] = valid ? nnext : 0;          // invalid -> entry 1 -> node 0, unmasked
        if (valid && pair < nnext) maskbits |= (1u << lvl);
        ncur = nnext;
    }

    int qoff = ((b * N_ + n) * H_ + h) * D_;
    float qa = Q[qoff + lane], qb = Q[qoff + lane + 32];

    float s[NCOLS];
#pragma unroll
    for (int l = 0; l < NCOLS; l++) {
        int g = node[l];
        const float* kp = (g < N_)
            ? (K + ((b * N_ + g) * H_ + h) * D_)
            : (g_nodeK + ((b * (N_ - 1) + (g - N_)) * H_ + h) * D_);
        s[l] = qa * kp[lane] + qb * kp[lane + 32];
    }
#pragma unroll
    for (int l = 0; l < NCOLS; l++) s[l] = warpReduceSum(s[l]) * SCALE;

    float m = -INFINITY;
#pragma unroll
    for (int l = 0; l < NCOLS; l++)
        if (!((maskbits >> l) & 1u)) m = fmaxf(m, s[l]);

    float sum = 0.0f;
#pragma unroll
    for (int l = 0; l < NCOLS; l++) {
        float w = ((maskbits >> l) & 1u) ? 0.0f : expf(s[l] - m);
        s[l] = w;
        sum += w;
    }
    float inv = 1.0f / sum;

    float oa = 0.0f, ob = 0.0f;
#pragma unroll
    for (int l = 0; l < NCOLS; l++) {
        int g = node[l];
        const float* vp = (g < N_)
            ? (V + ((b * N_ + g) * H_ + h) * D_)
            : (g_nodeV + ((b * (N_ - 1) + (g - N_)) * H_ + h) * D_);
        oa += s[l] * vp[lane];
        ob += s[l] * vp[lane + 32];
    }
    out[qoff + lane]      = oa * inv;
    out[qoff + lane + 32] = ob * inv;
}

extern "C" void kernel_launch(void* const* d_in, const int* in_sizes, int n_in,
                              void* d_out, int out_size)
{
    const float* Q = (const float*)d_in[0];
    const float* K = (const float*)d_in[1];
    const float* V = (const float*)d_in[2];
    float* out = (float*)d_out;

    // Build tree levels 1..11 (level-sequential).
    for (int l = 1; l <= 11; l++) {
        int P = N_ >> l;
        int parentBase = N_ - (N_ >> (l - 1));
        int childIsLeaf = (l == 1) ? 1 : 0;
        int childNN   = childIsLeaf ? N_ : (N_ - 1);
        int childBase = childIsLeaf ? 0  : (N_ - (N_ >> (l - 2)));
        int totalWarps = B_ * H_ * P;
        int threads = 256;
        int blocks = (totalWarps * 32 + threads - 1) / threads;
        build_level_kernel<<<blocks, threads>>>(K, V, childIsLeaf,
                                                childNN, childBase, parentBase, P);
    }

    // Attention over the 12-node hierarchical neighborhood.
    {
        int totalWarps = B_ * N_ * H_;
        int threads = 256;
        int blocks = (totalWarps * 32 + threads - 1) / threads;
        attn_kernel<<<blocks, threads>>>(Q, K, V, out);
    }
}

// round 3
// speedup vs baseline: 1.1795x; 1.1795x over previous
#include <cuda_runtime.h>
#include <math.h>

#define B_ 2
#define N_ 2048
#define H_ 16
#define D_ 64
#define NCOLS 12          // log2(N)+1
#define SCALE 0.125f      // 1/sqrt(64)
#define CHUNK 64
#define NCHUNK (N_ / CHUNK)   // 32

// Parent-node scratch: nodes N_ .. 2N_-2, layout [B, node-N_, H, D]
__device__ float g_nodeK[B_ * (N_ - 1) * H_ * D_];
__device__ float g_nodeV[B_ * (N_ - 1) * H_ * D_];

__device__ __forceinline__ float warpReduceSum(float v) {
    v += __shfl_xor_sync(0xffffffffu, v, 16);
    v += __shfl_xor_sync(0xffffffffu, v, 8);
    v += __shfl_xor_sync(0xffffffffu, v, 4);
    v += __shfl_xor_sync(0xffffffffu, v, 2);
    v += __shfl_xor_sync(0xffffffffu, v, 1);
    return v;
}

// 3-way softmax parent mix from two smem child rows (64 floats each).
__device__ __forceinline__ void compute_parent(
    const float* k0, const float* k1,
    const float* v0, const float* v1,
    int lane, float& Ka, float& Kb, float& Va, float& Vb)
{
    float k0a = k0[lane], k0b = k0[lane + 32];
    float k1a = k1[lane], k1b = k1[lane + 32];
    float v0a = v0[lane], v0b = v0[lane + 32];
    float v1a = v1[lane], v1b = v1[lane + 32];
    float kpa = 0.5f * (k0a + k1a), kpb = 0.5f * (k0b + k1b);
    float vpa = 0.5f * (v0a + v1a), vpb = 0.5f * (v0b + v1b);
    float ss = warpReduceSum(kpa * kpa + kpb * kpb) * SCALE;
    float s0 = warpReduceSum(kpa * k0a + kpb * k0b) * SCALE;
    float s1 = warpReduceSum(kpa * k1a + kpb * k1b) * SCALE;
    float m = fmaxf(ss, fmaxf(s0, s1));
    float es = __expf(ss - m), e0 = __expf(s0 - m), e1 = __expf(s1 - m);
    float inv = 1.0f / (es + e0 + e1 + 1e-9f);
    float ws = es * inv, w0 = e0 * inv, w1 = e1 * inv;
    Ka = ws * kpa + w0 * k0a + w1 * k1a;
    Kb = ws * kpb + w0 * k0b + w1 * k1b;
    Va = ws * vpa + w0 * v0a + w1 * v1a;
    Vb = ws * vpb + w0 * v0b + w1 * v1b;
}

// Kernel A: each block owns a 64-leaf chunk of one (b,h); builds levels 1..6 in smem.
__global__ __launch_bounds__(256) void build_lower(const float* __restrict__ K,
                                                   const float* __restrict__ V)
{
    __shared__ float sK[96 * 64];   // 24 KB
    __shared__ float sV[96 * 64];   // 24 KB
    int c = blockIdx.x % NCHUNK;
    int h = (blockIdx.x / NCHUNK) % H_;
    int b = blockIdx.x / (NCHUNK * H_);
    int tid = threadIdx.x, lane = tid & 31, warp = tid >> 5;

    // Stage 64 leaves (K,V) into smem slots 0..63 (float4 coalesced).
    for (int i = tid; i < CHUNK * 16; i += 256) {
        int node = i >> 4, d4 = i & 15;
        int off = (((b * N_ + c * CHUNK + node) * H_ + h) << 4) + d4;
        ((float4*)sK)[node * 16 + d4] = ((const float4*)K)[off];
        ((float4*)sV)[node * 16 + d4] = ((const float4*)V)[off];
    }
    __syncthreads();

    int curOff = 0;
    int P = CHUNK / 2;
    for (int lvl = 1; lvl <= 6; lvl++) {
        int parOff = (lvl & 1) ? 64 : 0;
        int base = N_ - (N_ >> (lvl - 1));
        for (int j = warp; j < P; j += 8) {
            float Ka, Kb, Va, Vb;
            const float* k0 = sK + (curOff + 2 * j) * 64;
            const float* v0 = sV + (curOff + 2 * j) * 64;
            compute_parent(k0, k0 + 64, v0, v0 + 64, lane, Ka, Kb, Va, Vb);
            sK[(parOff + j) * 64 + lane]      = Ka;
            sK[(parOff + j) * 64 + lane + 32] = Kb;
            sV[(parOff + j) * 64 + lane]      = Va;
            sV[(parOff + j) * 64 + lane + 32] = Vb;
            int jG = c * P + j;
            int po = ((b * (N_ - 1) + base + jG) * H_ + h) * D_;
            g_nodeK[po + lane]      = Ka; g_nodeK[po + lane + 32] = Kb;
            g_nodeV[po + lane]      = Va; g_nodeV[po + lane + 32] = Vb;
        }
        __syncthreads();
        curOff = parOff;
        P >>= 1;
    }
}

// Kernel B: one block per (b,h); builds levels 7..11 from the 32 level-6 nodes.
__global__ __launch_bounds__(256) void build_upper()
{
    __shared__ float sK[48 * 64];
    __shared__ float sV[48 * 64];
    int h = blockIdx.x % H_;
    int b = blockIdx.x / H_;
    int tid = threadIdx.x, lane = tid & 31, warp = tid >> 5;

    // Load the 32 level-6 nodes (scratch-local base = 1984).
    for (int i = tid; i < 32 * 16; i += 256) {
        int node = i >> 4, d4 = i & 15;
        int off = (((b * (N_ - 1) + 1984 + node) * H_ + h) << 4) + d4;
        ((float4*)sK)[node * 16 + d4] = ((const float4*)g_nodeK)[off];
        ((float4*)sV)[node * 16 + d4] = ((const float4*)g_nodeV)[off];
    }
    __syncthreads();

    int curOff = 0;
    int P = 16;
    for (int lvl = 7; lvl <= 11; lvl++) {
        int parOff = (lvl & 1) ? 32 : 0;
        int base = N_ - (N_ >> (lvl - 1));
        // BUGFIX (R2): lvl7 has P=16 > 8 warps — must stride, not `if (warp < P)`.
        for (int j = warp; j < P; j += 8) {
            float Ka, Kb, Va, Vb;
            const float* k0 = sK + (curOff + 2 * j) * 64;
            const float* v0 = sV + (curOff + 2 * j) * 64;
            compute_parent(k0, k0 + 64, v0, v0 + 64, lane, Ka, Kb, Va, Vb);
            sK[(parOff + j) * 64 + lane]      = Ka;
            sK[(parOff + j) * 64 + lane + 32] = Kb;
            sV[(parOff + j) * 64 + lane]      = Va;
            sV[(parOff + j) * 64 + lane + 32] = Vb;
            int po = ((b * (N_ - 1) + base + j) * H_ + h) * D_;
            g_nodeK[po + lane]      = Ka; g_nodeK[po + lane + 32] = Kb;
            g_nodeV[po + lane]      = Va; g_nodeV[po + lane + 32] = Vb;
        }
        __syncthreads();
        curOff = parOff;
        P >>= 1;
    }
}

// Attention: block = 8 warps = 8 CONSECUTIVE queries n of one (b,h).
// Level-l table entry depends only on n>>(l-1), so levels >=4 are shared
// by all warps in the block -> L1 reuse on the gathers.
__global__ __launch_bounds__(256) void attn_kernel(const float* __restrict__ Q,
                                                   const float* __restrict__ K,
                                                   const float* __restrict__ V,
                                                   float* __restrict__ out)
{
    int lane = threadIdx.x & 31;
    int warp = threadIdx.x >> 5;
    int nc = blockIdx.x % (N_ / 8);
    int h  = (blockIdx.x / (N_ / 8)) % H_;
    int b  = blockIdx.x / ((N_ / 8) * H_);
    int n  = nc * 8 + warp;

    // In-register hierarchical index table (faithful to _build_idx_table).
    int node[NCOLS];
    unsigned maskbits = 0u;
    node[0] = n;
    int ncur = n;
#pragma unroll
    for (int lvl = 1; lvl < NCOLS; lvl++) {
        int pair, nnext;
        if (lvl == 1) { nnext = ncur ^ 1; pair = ncur; }
        else          { pair = (ncur >> 1) + N_; nnext = pair ^ 1; }
        bool valid = (nnext <= 2 * N_ - 3);
        node[lvl] = valid ? nnext : 0;          // invalid -> entry 1 -> node 0, unmasked
        if (valid && pair < nnext) maskbits |= (1u << lvl);
        ncur = nnext;
    }

    int qoff = ((b * N_ + n) * H_ + h) * D_;
    float qa = Q[qoff + lane], qb = Q[qoff + lane + 32];

    float s[NCOLS];
#pragma unroll
    for (int l = 0; l < NCOLS; l++) {
        int g = node[l];
        const float* kp = (g < N_)
            ? (K + ((b * N_ + g) * H_ + h) * D_)
            : (g_nodeK + ((b * (N_ - 1) + (g - N_)) * H_ + h) * D_);
        s[l] = qa * kp[lane] + qb * kp[lane + 32];
    }
#pragma unroll
    for (int l = 0; l < NCOLS; l++) s[l] = warpReduceSum(s[l]) * SCALE;

    float m = -INFINITY;
#pragma unroll
    for (int l = 0; l < NCOLS; l++)
        if (!((maskbits >> l) & 1u)) m = fmaxf(m, s[l]);

    float sum = 0.0f;
#pragma unroll
    for (int l = 0; l < NCOLS; l++) {
        float w = ((maskbits >> l) & 1u) ? 0.0f : __expf(s[l] - m);
        s[l] = w;
        sum += w;
    }
    float inv = 1.0f / sum;

    float oa = 0.0f, ob = 0.0f;
#pragma unroll
    for (int l = 0; l < NCOLS; l++) {
        int g = node[l];
        const float* vp = (g < N_)
            ? (V + ((b * N_ + g) * H_ + h) * D_)
            : (g_nodeV + ((b * (N_ - 1) + (g - N_)) * H_ + h) * D_);
        oa += s[l] * vp[lane];
        ob += s[l] * vp[lane + 32];
    }
    out[qoff + lane]      = oa * inv;
    out[qoff + lane + 32] = ob * inv;
}

extern "C" void kernel_launch(void* const* d_in, const int* in_sizes, int n_in,
                              void* d_out, int out_size)
{
    const float* Q = (const float*)d_in[0];
    const float* K = (const float*)d_in[1];
    const float* V = (const float*)d_in[2];
    float* out = (float*)d_out;

    build_lower<<<B_ * H_ * NCHUNK, 256>>>(K, V);   // levels 1..6
    build_upper<<<B_ * H_, 256>>>();                 // levels 7..11
    attn_kernel<<<B_ * H_ * (N_ / 8), 256>>>(Q, K, V, out);
}

// round 4
// speedup vs baseline: 1.2239x; 1.0377x over previous
#include <cuda_runtime.h>
#include <math.h>

#define B_ 2
#define N_ 2048
#define H_ 16
#define D_ 64
#define NCOLS 12          // log2(N)+1
#define SCALE 0.125f      // 1/sqrt(64)
#define CHUNK 64
#define NCHUNK (N_ / CHUNK)   // 32

// Parent-node scratch: nodes N_ .. 2N_-2, layout [B, node-N_, H, D], float4 (16/row)
__device__ float4 g_nodeK4[B_ * (N_ - 1) * H_ * 16];
__device__ float4 g_nodeV4[B_ * (N_ - 1) * H_ * 16];

// 4-step reduction within a 16-lane half-warp (xor offsets < 16 never cross halves).
__device__ __forceinline__ float halfReduce(float v, unsigned hmask) {
    v += __shfl_xor_sync(hmask, v, 8);
    v += __shfl_xor_sync(hmask, v, 4);
    v += __shfl_xor_sync(hmask, v, 2);
    v += __shfl_xor_sync(hmask, v, 1);
    return v;
}

__device__ __forceinline__ float dot4(float4 a, float4 b) {
    return a.x * b.x + a.y * b.y + a.z * b.z + a.w * b.w;
}

// 3-way softmax parent mix; one 16-lane half-warp per parent, float4 per lane.
// Uses s1 = 2*ss - s0 (exact algebra: kp = 0.5(k0+k1) => s0+s1 = 2*ss).
__device__ __forceinline__ void parent_mix_f4(float4 k0, float4 k1, float4 v0, float4 v1,
                                              unsigned hmask, float4& Ko, float4& Vo)
{
    float4 kp = make_float4(0.5f * (k0.x + k1.x), 0.5f * (k0.y + k1.y),
                            0.5f * (k0.z + k1.z), 0.5f * (k0.w + k1.w));
    float4 vp = make_float4(0.5f * (v0.x + v1.x), 0.5f * (v0.y + v1.y),
                            0.5f * (v0.z + v1.z), 0.5f * (v0.w + v1.w));
    float ss = halfReduce(dot4(kp, kp), hmask) * SCALE;
    float s0 = halfReduce(dot4(kp, k0), hmask) * SCALE;
    float s1 = 2.0f * ss - s0;
    float m = fmaxf(ss, fmaxf(s0, s1));
    float es = __expf(ss - m), e0 = __expf(s0 - m), e1 = __expf(s1 - m);
    float inv = 1.0f / (es + e0 + e1 + 1e-9f);
    float ws = es * inv, w0 = e0 * inv, w1 = e1 * inv;
    Ko = make_float4(ws * kp.x + w0 * k0.x + w1 * k1.x,
                     ws * kp.y + w0 * k0.y + w1 * k1.y,
                     ws * kp.z + w0 * k0.z + w1 * k1.z,
                     ws * kp.w + w0 * k0.w + w1 * k1.w);
    Vo = make_float4(ws * vp.x + w0 * v0.x + w1 * v1.x,
                     ws * vp.y + w0 * v0.y + w1 * v1.y,
                     ws * vp.z + w0 * v0.z + w1 * v1.z,
                     ws * vp.w + w0 * v0.w + w1 * v1.w);
}

// Kernel A: block owns a 64-leaf chunk of one (b,h); builds levels 1..6 in smem.
// 512 threads = 32 half-warps; one half-warp per parent.
__global__ __launch_bounds__(512) void build_lower(const float* __restrict__ K,
                                                   const float* __restrict__ V)
{
    __shared__ float4 sK[96 * 16];   // 24 KB
    __shared__ float4 sV[96 * 16];   // 24 KB
    int c = blockIdx.x % NCHUNK;
    int h = (blockIdx.x / NCHUNK) % H_;
    int b = blockIdx.x / (NCHUNK * H_);
    int tid = threadIdx.x, lane = tid & 31, warp = tid >> 5;
    int c16 = lane & 15;
    int halfIdx = warp * 2 + (lane >> 4);
    unsigned hmask = 0xFFFFu << (lane & 16);

    const float4* K4 = (const float4*)K;
    const float4* V4 = (const float4*)V;

    // Stage 64 leaves (float4 coalesced).
    for (int i = tid; i < CHUNK * 16; i += 512) {
        int node = i >> 4, d4 = i & 15;
        int off = ((b * N_ + c * CHUNK + node) * H_ + h) * 16 + d4;
        sK[i] = K4[off];
        sV[i] = V4[off];
    }
    __syncthreads();

    int curOff = 0;
    int P = CHUNK / 2;   // 32
    for (int lvl = 1; lvl <= 6; lvl++) {
        int parOff = (lvl & 1) ? 64 : 0;
        int base = N_ - (N_ >> (lvl - 1));
        for (int j = halfIdx; j < P; j += 32) {
            float4 k0 = sK[(curOff + 2 * j) * 16 + c16];
            float4 k1 = sK[(curOff + 2 * j + 1) * 16 + c16];
            float4 v0 = sV[(curOff + 2 * j) * 16 + c16];
            float4 v1 = sV[(curOff + 2 * j + 1) * 16 + c16];
            float4 Ko, Vo;
            parent_mix_f4(k0, k1, v0, v1, hmask, Ko, Vo);
            sK[(parOff + j) * 16 + c16] = Ko;
            sV[(parOff + j) * 16 + c16] = Vo;
            int jG = c * P + j;
            int po = ((b * (N_ - 1) + base + jG) * H_ + h) * 16 + c16;
            g_nodeK4[po] = Ko;
            g_nodeV4[po] = Vo;
        }
        __syncthreads();
        curOff = parOff;
        P >>= 1;
    }
}

// Kernel B: one block per (b,h); builds levels 7..11 from the 32 level-6 nodes.
// 256 threads = 16 half-warps.
__global__ __launch_bounds__(256) void build_upper()
{
    __shared__ float4 sK[48 * 16];
    __shared__ float4 sV[48 * 16];
    int h = blockIdx.x % H_;
    int b = blockIdx.x / H_;
    int tid = threadIdx.x, lane = tid & 31, warp = tid >> 5;
    int c16 = lane & 15;
    int halfIdx = warp * 2 + (lane >> 4);
    unsigned hmask = 0xFFFFu << (lane & 16);

    // Load the 32 level-6 nodes (scratch-local base = 1984).
    for (int i = tid; i < 32 * 16; i += 256) {
        int node = i >> 4, d4 = i & 15;
        int off = ((b * (N_ - 1) + 1984 + node) * H_ + h) * 16 + d4;
        sK[i] = g_nodeK4[off];
        sV[i] = g_nodeV4[off];
    }
    __syncthreads();

    int curOff = 0;
    int P = 16;
    for (int lvl = 7; lvl <= 11; lvl++) {
        int parOff = (lvl & 1) ? 32 : 0;
        int base = N_ - (N_ >> (lvl - 1));
        for (int j = halfIdx; j < P; j += 16) {
            float4 k0 = sK[(curOff + 2 * j) * 16 + c16];
            float4 k1 = sK[(curOff + 2 * j + 1) * 16 + c16];
            float4 v0 = sV[(curOff + 2 * j) * 16 + c16];
            float4 v1 = sV[(curOff + 2 * j + 1) * 16 + c16];
            float4 Ko, Vo;
            parent_mix_f4(k0, k1, v0, v1, hmask, Ko, Vo);
            sK[(parOff + j) * 16 + c16] = Ko;
            sV[(parOff + j) * 16 + c16] = Vo;
            int po = ((b * (N_ - 1) + base + j) * H_ + h) * 16 + c16;
            g_nodeK4[po] = Ko;
            g_nodeV4[po] = Vo;
        }
        __syncthreads();
        curOff = parOff;
        P >>= 1;
    }
}

// Attention: one 16-lane half-warp per query; block = 8 warps = 16 consecutive n
// of one (b,h) -> gather reuse for shared upper-level nodes.
__global__ __launch_bounds__(256) void attn_kernel(const float* __restrict__ Q,
                                                   const float* __restrict__ K,
                                                   const float* __restrict__ V,
                                                   float* __restrict__ out)
{
    int tid = threadIdx.x;
    int lane = tid & 31;
    int warp = tid >> 5;
    int c16 = lane & 15;
    unsigned hmask = 0xFFFFu << (lane & 16);

    int nc = blockIdx.x % (N_ / 16);
    int h  = (blockIdx.x / (N_ / 16)) % H_;
    int b  = blockIdx.x / ((N_ / 16) * H_);
    int n  = nc * 16 + warp * 2 + (lane >> 4);

    // In-register hierarchical index table (faithful to _build_idx_table).
    int node[NCOLS];
    unsigned maskbits = 0u;
    node[0] = n;
    int ncur = n;
#pragma unroll
    for (int lvl = 1; lvl < NCOLS; lvl++) {
        int pair, nnext;
        if (lvl == 1) { nnext = ncur ^ 1; pair = ncur; }
        else          { pair = (ncur >> 1) + N_; nnext = pair ^ 1; }
        bool valid = (nnext <= 2 * N_ - 3);
        node[lvl] = valid ? nnext : 0;          // invalid -> entry 1 -> node 0, unmasked
        if (valid && pair < nnext) maskbits |= (1u << lvl);
        ncur = nnext;
    }

    const float4* Q4 = (const float4*)Q;
    const float4* K4 = (const float4*)K;
    const float4* V4 = (const float4*)V;

    int qbase = ((b * N_ + n) * H_ + h) * 16;
    float4 q = Q4[qbase + c16];

    // Gather K rows (one LDG.128 per row per half-warp), compute partial dots.
    float4 kreg[NCOLS];
#pragma unroll
    for (int l = 0; l < NCOLS; l++) {
        int g = node[l];
        const float4* kp = (g < N_)
            ? (K4 + ((b * N_ + g) * H_ + h) * 16)
            : (g_nodeK4 + ((b * (N_ - 1) + (g - N_)) * H_ + h) * 16);
        kreg[l] = kp[c16];
    }
    float s[NCOLS];
#pragma unroll
    for (int l = 0; l < NCOLS; l++) s[l] = dot4(q, kreg[l]);

    // Issue V gathers before the reduction/softmax to overlap latency.
    float4 vreg[NCOLS];
#pragma unroll
    for (int l = 0; l < NCOLS; l++) {
        int g = node[l];
        const float4* vp = (g < N_)
            ? (V4 + ((b * N_ + g) * H_ + h) * 16)
            : (g_nodeV4 + ((b * (N_ - 1) + (g - N_)) * H_ + h) * 16);
        vreg[l] = vp[c16];
    }

#pragma unroll
    for (int l = 0; l < NCOLS; l++) s[l] = halfReduce(s[l], hmask) * SCALE;

    float m = -INFINITY;
#pragma unroll
    for (int l = 0; l < NCOLS; l++)
        if (!((maskbits >> l) & 1u)) m = fmaxf(m, s[l]);

    float sum = 0.0f;
#pragma unroll
    for (int l = 0; l < NCOLS; l++) {
        float w = ((maskbits >> l) & 1u) ? 0.0f : __expf(s[l] - m);
        s[l] = w;
        sum += w;
    }
    float inv = 1.0f / sum;

    float4 o = make_float4(0.f, 0.f, 0.f, 0.f);
#pragma unroll
    for (int l = 0; l < NCOLS; l++) {
        o.x += s[l] * vreg[l].x;
        o.y += s[l] * vreg[l].y;
        o.z += s[l] * vreg[l].z;
        o.w += s[l] * vreg[l].w;
    }
    float4* out4 = (float4*)out;
    out4[qbase + c16] = make_float4(o.x * inv, o.y * inv, o.z * inv, o.w * inv);
}

extern "C" void kernel_launch(void* const* d_in, const int* in_sizes, int n_in,
                              void* d_out, int out_size)
{
    const float* Q = (const float*)d_in[0];
    const float* K = (const float*)d_in[1];
    const float* V = (const float*)d_in[2];
    float* out = (float*)d_out;

    build_lower<<<B_ * H_ * NCHUNK, 512>>>(K, V);    // levels 1..6
    build_upper<<<B_ * H_, 256>>>();                  // levels 7..11
    attn_kernel<<<B_ * H_ * (N_ / 16), 256>>>(Q, K, V, out);
}

// round 5
// speedup vs baseline: 1.4127x; 1.1543x over previous
#include <cuda_runtime.h>
#include <math.h>

#define B_ 2
#define N_ 2048
#define H_ 16
#define NCOLS 12          // log2(N)+1
#define SCALE 0.125f      // 1/sqrt(64)
#define CHUNK 64
#define NCHUNK 32         // N_/CHUNK

// Only the 32 level-6 chunk-root nodes per (b,h) ever touch global memory.
__device__ float4 g_L6K4[B_ * H_ * NCHUNK * 16];
__device__ float4 g_L6V4[B_ * H_ * NCHUNK * 16];

// smem row map (per tensor), 188 rows of 16 float4:
//  0..63   leaves            64..95  L1     96..111 L2    112..119 L3
//  120..123 L4               124..125 L5    126..157 L6 (all 32 chunks)
//  158..173 L7               174..181 L8    182..185 L9   186..187 L10
#define ROWS_T 188

__device__ __forceinline__ float halfReduce(float v, unsigned hmask) {
    v += __shfl_xor_sync(hmask, v, 8);
    v += __shfl_xor_sync(hmask, v, 4);
    v += __shfl_xor_sync(hmask, v, 2);
    v += __shfl_xor_sync(hmask, v, 1);
    return v;
}

__device__ __forceinline__ float dot4(float4 a, float4 b) {
    return a.x * b.x + a.y * b.y + a.z * b.z + a.w * b.w;
}

// 3-way softmax parent mix; 16-lane half-warp, float4/lane.
// Exact algebra: kp = 0.5(k0+k1) => s0 + s1 = 2*ss, so s1 = 2*ss - s0.
__device__ __forceinline__ void parent_mix_f4(float4 k0, float4 k1, float4 v0, float4 v1,
                                              unsigned hmask, float4& Ko, float4& Vo)
{
    float4 kp = make_float4(0.5f * (k0.x + k1.x), 0.5f * (k0.y + k1.y),
                            0.5f * (k0.z + k1.z), 0.5f * (k0.w + k1.w));
    float4 vp = make_float4(0.5f * (v0.x + v1.x), 0.5f * (v0.y + v1.y),
                            0.5f * (v0.z + v1.z), 0.5f * (v0.w + v1.w));
    float ss = halfReduce(dot4(kp, kp), hmask) * SCALE;
    float s0 = halfReduce(dot4(kp, k0), hmask) * SCALE;
    float s1 = 2.0f * ss - s0;
    float m = fmaxf(ss, fmaxf(s0, s1));
    float es = __expf(ss - m), e0 = __expf(s0 - m), e1 = __expf(s1 - m);
    float inv = 1.0f / (es + e0 + e1 + 1e-9f);
    float ws = es * inv, w0 = e0 * inv, w1 = e1 * inv;
    Ko = make_float4(ws * kp.x + w0 * k0.x + w1 * k1.x,
                     ws * kp.y + w0 * k0.y + w1 * k1.y,
                     ws * kp.z + w0 * k0.z + w1 * k1.z,
                     ws * kp.w + w0 * k0.w + w1 * k1.w);
    Vo = make_float4(ws * vp.x + w0 * v0.x + w1 * v1.x,
                     ws * vp.y + w0 * v0.y + w1 * v1.y,
                     ws * vp.z + w0 * v0.z + w1 * v1.z,
                     ws * vp.w + w0 * v0.w + w1 * v1.w);
}

// k1: per 64-leaf chunk, build levels 1..6 in smem; emit ONLY the level-6 node.
__global__ __launch_bounds__(512) void build_chunk_root(const float* __restrict__ K,
                                                        const float* __restrict__ V)
{
    __shared__ float4 sK[96 * 16];   // 24 KB
    __shared__ float4 sV[96 * 16];   // 24 KB
    int c = blockIdx.x % NCHUNK;
    int h = (blockIdx.x / NCHUNK) % H_;
    int b = blockIdx.x / (NCHUNK * H_);
    int tid = threadIdx.x, lane = tid & 31, warp = tid >> 5;
    int c16 = lane & 15;
    int halfIdx = warp * 2 + (lane >> 4);
    unsigned hmask = 0xFFFFu << (lane & 16);

    const float4* K4 = (const float4*)K;
    const float4* V4 = (const float4*)V;

    for (int i = tid; i < CHUNK * 16; i += 512) {
        int node = i >> 4, d4 = i & 15;
        int off = ((b * N_ + c * CHUNK + node) * H_ + h) * 16 + d4;
        sK[i] = K4[off];
        sV[i] = V4[off];
    }
    __syncthreads();

    int curOff = 0, P = 32;
    for (int lvl = 1; lvl <= 6; lvl++) {
        int parOff = (lvl & 1) ? 64 : 0;
        if (halfIdx < P) {
            int j = halfIdx;
            float4 k0 = sK[(curOff + 2 * j) * 16 + c16];
            float4 k1 = sK[(curOff + 2 * j + 1) * 16 + c16];
            float4 v0 = sV[(curOff + 2 * j) * 16 + c16];
            float4 v1 = sV[(curOff + 2 * j + 1) * 16 + c16];
            float4 Ko, Vo;
            parent_mix_f4(k0, k1, v0, v1, hmask, Ko, Vo);
            if (lvl < 6) {
                sK[(parOff + j) * 16 + c16] = Ko;
                sV[(parOff + j) * 16 + c16] = Vo;
            } else {
                g_L6K4[((b * H_ + h) * NCHUNK + c) * 16 + c16] = Ko;
                g_L6V4[((b * H_ + h) * NCHUNK + c) * 16 + c16] = Vo;
            }
        }
        __syncthreads();
        curOff = parOff;
        P >>= 1;
    }
}

// k3: fused re-build (levels 1..5 local, 7..10 from global L6) + attention.
// Block = one 64-leaf chunk of one (b,h), 512 threads = 32 half-warps,
// 2 queries per half-warp, all K/V gathers from smem.
__global__ __launch_bounds__(512) void fused_attn(const float* __restrict__ Q,
                                                  const float* __restrict__ K,
                                                  const float* __restrict__ V,
                                                  float* __restrict__ out)
{
    extern __shared__ float4 smem[];
    float4* sK = smem;
    float4* sV = smem + ROWS_T * 16;

    int c = blockIdx.x % NCHUNK;
    int h = (blockIdx.x / NCHUNK) % H_;
    int b = blockIdx.x / (NCHUNK * H_);
    int tid = threadIdx.x, lane = tid & 31, warp = tid >> 5;
    int c16 = lane & 15;
    int halfIdx = warp * 2 + (lane >> 4);
    unsigned hmask = 0xFFFFu << (lane & 16);

    const float4* Q4 = (const float4*)Q;
    const float4* K4 = (const float4*)K;
    const float4* V4 = (const float4*)V;
    float4* out4 = (float4*)out;

    // Stage 64 leaves + all 32 level-6 nodes.
    for (int i = tid; i < CHUNK * 16; i += 512) {
        int node = i >> 4, d4 = i & 15;
        int off = ((b * N_ + c * CHUNK + node) * H_ + h) * 16 + d4;
        sK[i] = K4[off];
        sV[i] = V4[off];
    }
    for (int i = tid; i < NCHUNK * 16; i += 512) {
        int node = i >> 4, d4 = i & 15;
        int off = ((b * H_ + h) * NCHUNK + node) * 16 + d4;
        sK[(126 + node) * 16 + d4] = g_L6K4[off];
        sV[(126 + node) * 16 + d4] = g_L6V4[off];
    }
    __syncthreads();

    // Interleaved level rounds: (L1|L7), (L2|L8), (L3|L9), (L4|L10), (L5).
    // Round 1: L1 (32 parents, children = leaf rows) + L7 (16, children = L6 rows).
    for (int t = halfIdx; t < 48; t += 32) {
        int cb, pr;
        if (t < 32) { cb = 2 * t;              pr = 64 + t; }
        else        { cb = 126 + 2 * (t - 32); pr = 158 + (t - 32); }
        float4 Ko, Vo;
        parent_mix_f4(sK[cb * 16 + c16], sK[(cb + 1) * 16 + c16],
                      sV[cb * 16 + c16], sV[(cb + 1) * 16 + c16], hmask, Ko, Vo);
        sK[pr * 16 + c16] = Ko;
        sV[pr * 16 + c16] = Vo;
    }
    __syncthreads();
    // Round 2: L2 (16) + L8 (8)
    if (halfIdx < 24) {
        int cb, pr;
        if (halfIdx < 16) { cb = 64 + 2 * halfIdx;         pr = 96 + halfIdx; }
        else              { int j = halfIdx - 16; cb = 158 + 2 * j; pr = 174 + j; }
        float4 Ko, Vo;
        parent_mix_f4(sK[cb * 16 + c16], sK[(cb + 1) * 16 + c16],
                      sV[cb * 16 + c16], sV[(cb + 1) * 16 + c16], hmask, Ko, Vo);
        sK[pr * 16 + c16] = Ko;
        sV[pr * 16 + c16] = Vo;
    }
    __syncthreads();
    // Round 3: L3 (8) + L9 (4)
    if (halfIdx < 12) {
        int cb, pr;
        if (halfIdx < 8) { cb = 96 + 2 * halfIdx;          pr = 112 + halfIdx; }
        else             { int j = halfIdx - 8; cb = 174 + 2 * j; pr = 182 + j; }
        float4 Ko, Vo;
        parent_mix_f4(sK[cb * 16 + c16], sK[(cb + 1) * 16 + c16],
                      sV[cb * 16 + c16], sV[(cb + 1) * 16 + c16], hmask, Ko, Vo);
        sK[pr * 16 + c16] = Ko;
        sV[pr * 16 + c16] = Vo;
    }
    __syncthreads();
    // Round 4: L4 (4) + L10 (2)
    if (halfIdx < 6) {
        int cb, pr;
        if (halfIdx < 4) { cb = 112 + 2 * halfIdx;         pr = 120 + halfIdx; }
        else             { int j = halfIdx - 4; cb = 182 + 2 * j; pr = 186 + j; }
        float4 Ko, Vo;
        parent_mix_f4(sK[cb * 16 + c16], sK[(cb + 1) * 16 + c16],
                      sV[cb * 16 + c16], sV[(cb + 1) * 16 + c16], hmask, Ko, Vo);
        sK[pr * 16 + c16] = Ko;
        sV[pr * 16 + c16] = Vo;
    }
    __syncthreads();
    // Round 5: L5 (2)
    if (halfIdx < 2) {
        int cb = 120 + 2 * halfIdx, pr = 124 + halfIdx;
        float4 Ko, Vo;
        parent_mix_f4(sK[cb * 16 + c16], sK[(cb + 1) * 16 + c16],
                      sV[cb * 16 + c16], sV[(cb + 1) * 16 + c16], hmask, Ko, Vo);
        sK[pr * 16 + c16] = Ko;
        sV[pr * 16 + c16] = Vo;
    }
    __syncthreads();

    // ---- Attention: 2 queries per half-warp, everything from smem ----
    // Tree-level bases within the global node numbering (node - N_):
    const int baseL[11] = {0, 0, 1024, 1536, 1792, 1920, 1984, 2016, 2032, 2040, 2044};
    const int rowB[11]  = {0, 64, 96, 112, 120, 124, 126, 158, 174, 182, 186};

#pragma unroll
    for (int u = 0; u < 2; u++) {
        int q = halfIdx + 32 * u;
        int n = c * CHUNK + q;

        int row[NCOLS];
        unsigned maskbits = 0u;
        row[0] = q;
        int ncur = n;
#pragma unroll
        for (int lvl = 1; lvl < NCOLS; lvl++) {
            int pair, nnext;
            if (lvl == 1) {
                nnext = ncur ^ 1; pair = ncur;
                row[1] = nnext & (CHUNK - 1);
            } else {
                pair = (ncur >> 1) + N_;
                nnext = pair ^ 1;
                int L = lvl - 1;
                int jL = nnext - N_ - baseL[L];
                row[lvl] = rowB[L] + jL - ((L <= 5) ? (c << (6 - L)) : 0);
            }
            if (pair < nnext) maskbits |= (1u << lvl);
            ncur = nnext;
        }

        int qbase = ((b * N_ + n) * H_ + h) * 16;
        float4 qv = Q4[qbase + c16];

        float s[NCOLS];
#pragma unroll
        for (int l = 0; l < NCOLS; l++)
            s[l] = dot4(qv, sK[row[l] * 16 + c16]);
#pragma unroll
        for (int l = 0; l < NCOLS; l++)
            s[l] = halfReduce(s[l], hmask) * SCALE;

        float m = -INFINITY;
#pragma unroll
        for (int l = 0; l < NCOLS; l++)
            if (!((maskbits >> l) & 1u)) m = fmaxf(m, s[l]);

        float sum = 0.0f;
#pragma unroll
        for (int l = 0; l < NCOLS; l++) {
            float w = ((maskbits >> l) & 1u) ? 0.0f : __expf(s[l] - m);
            s[l] = w;
            sum += w;
        }
        float inv = 1.0f / sum;

        float4 o = make_float4(0.f, 0.f, 0.f, 0.f);
#pragma unroll
        for (int l = 0; l < NCOLS; l++) {
            float4 v = sV[row[l] * 16 + c16];
            o.x += s[l] * v.x;
            o.y += s[l] * v.y;
            o.z += s[l] * v.z;
            o.w += s[l] * v.w;
        }
        out4[qbase + c16] = make_float4(o.x * inv, o.y * inv, o.z * inv, o.w * inv);
    }
}

extern "C" void kernel_launch(void* const* d_in, const int* in_sizes, int n_in,
                              void* d_out, int out_size)
{
    const float* Q = (const float*)d_in[0];
    const float* K = (const float*)d_in[1];
    const float* V = (const float*)d_in[2];
    float* out = (float*)d_out;

    const int smemBytes = 2 * ROWS_T * 16 * (int)sizeof(float4);   // 96256 B
    static int attrSet = 0;
    if (!attrSet) {
        cudaFuncSetAttribute(fused_attn, cudaFuncAttributeMaxDynamicSharedMemorySize, smemBytes);
        attrSet = 1;
    }

    build_chunk_root<<<B_ * H_ * NCHUNK, 512>>>(K, V);
    fused_attn<<<B_ * H_ * NCHUNK, 512, smemBytes>>>(Q, K, V, out);
}